// round 8
// baseline (speedup 1.0000x reference)
#include <cuda_runtime.h>
#include <cstdint>
#include <cstddef>

#define CC  128
#define MT  128
#define NTH 256

#define CST 20                    // chunk row stride (floats), K16 chunks
#define HST 132                   // hidden [m][k] row stride (floats)
#define CHF (128 * CST)           // 2560 floats per chunk buffer
#define OFHf (4 * CHF)            // hidden offset = 10240 floats
#define SMEM_FLOATS (4 * CHF + 128 * HST)     // 27136
#define SMEM_BYTES  (SMEM_FLOATS * 4)         // 108544

// -------------------- device globals (no allocations allowed) --------------
__device__ float g_agg[40000 * CC];
__device__ float g_w1e[CC * 3 * CC];   // transposed [n][k], tf32-rounded
__device__ float g_w2e[CC * CC];
__device__ float g_w1n[CC * 2 * CC];
__device__ float g_w2n[CC * CC];

// -------------------- helpers ----------------------------------------------
__device__ __forceinline__ uint32_t rna(float x) {
    uint32_t u; asm("cvt.rna.tf32.f32 %0, %1;" : "=r"(u) : "f"(x)); return u;
}
__device__ __forceinline__ uint32_t su32(const void* p) {
    return (uint32_t)__cvta_generic_to_shared(p);
}
__device__ __forceinline__ void mma_t(float* c, const uint32_t* a, const uint32_t* b) {
    asm volatile(
        "mma.sync.aligned.m16n8k8.row.col.f32.tf32.tf32.f32 "
        "{%0,%1,%2,%3}, {%4,%5,%6,%7}, {%8,%9}, {%0,%1,%2,%3};"
        : "+f"(c[0]), "+f"(c[1]), "+f"(c[2]), "+f"(c[3])
        : "r"(a[0]), "r"(a[1]), "r"(a[2]), "r"(a[3]), "r"(b[0]), "r"(b[1]));
}
#define CP16(dst, src) \
    asm volatile("cp.async.cg.shared.global [%0], [%1], 16;" \
                 :: "r"(dst), "l"(src) : "memory")
#define CPCOMMIT() asm volatile("cp.async.commit_group;" ::: "memory")
#define CPWAIT0() asm volatile("cp.async.wait_group 0;" ::: "memory")
#define CPWAIT1() asm volatile("cp.async.wait_group 1;" ::: "memory")
#define CPWAIT2() asm volatile("cp.async.wait_group 2;" ::: "memory")

// -------------------- fused MLP kernel (tf32, pipelined) -------------------
template<int SEGS, bool EDGE>
__global__ __launch_bounds__(NTH, 2)
void mlp_tf32(const float* __restrict__ seg0, const int* __restrict__ idx0,
              const float* __restrict__ seg1, const int* __restrict__ idx1,
              const float* __restrict__ seg2,
              const float* __restrict__ W1, const float* __restrict__ W2,
              const float* __restrict__ B1, const float* __restrict__ B2,
              const float* __restrict__ G,  const float* __restrict__ BN,
              const float* __restrict__ resid,
              const int* __restrict__ aggidx, float* __restrict__ agg,
              float* __restrict__ out, int M)
{
    extern __shared__ __align__(16) float smf[];
    __shared__ int srow[3][MT];
    __shared__ int saggi[MT];
    __shared__ float sB1[CC], sB2[CC], sG[CC], sBN[CC];

    const int tid  = threadIdx.x;
    const int wid  = tid >> 5;
    const int lane = tid & 31;
    const int wm   = wid & 1;
    const int wn   = wid >> 1;
    const int tile0 = blockIdx.x * MT;
    const int K1 = SEGS * CC;
    const int r4 = lane >> 2;
    const int c4 = lane & 3;
    const int m2 = tid >> 1;         // 0..127: A row / weight row
    const int h2 = tid & 1;          // which 8-float half of the 16-k chunk
    const uint32_t sb = su32(smf);

    if (tid < MT) {
        int r = tile0 + tid;
        int rr = (r < M) ? r : (M - 1);
        srow[0][tid] = idx0 ? idx0[rr] : rr;
        srow[1][tid] = idx1 ? idx1[rr] : rr;
        srow[2][tid] = rr;
        if (EDGE) saggi[tid] = aggidx[rr];
        sB1[tid] = B1[tid]; sB2[tid] = B2[tid];
        sG[tid]  = G[tid];  sBN[tid] = BN[tid];
    }

    float acc[4][4][4];
#pragma unroll
    for (int i = 0; i < 4; i++)
#pragma unroll
        for (int j = 0; j < 4; j++)
#pragma unroll
            for (int k = 0; k < 4; k++) acc[i][j][k] = 0.f;

    __syncthreads();

    // ================= GEMM1: [128, SEGS*128] @ W1, K16 pipelined ==========
    const int NC1 = SEGS * 8;
    float4 rA0, rA1;
    // prologue: LDG A chunk 0; cp.async B chunk 0 -> Bbuf0
    {
        const float* pA = seg0 + (size_t)srow[0][m2] * CC + h2 * 8;
        rA0 = __ldg((const float4*)pA);
        rA1 = __ldg((const float4*)pA + 1);
        const float* pB = W1 + (size_t)m2 * K1 + h2 * 8;
        uint32_t bd = sb + (2 * CHF + m2 * CST + h2 * 8) * 4;
        CP16(bd, pB); CP16(bd + 16, pB + 4);
        CPCOMMIT();
    }
    for (int c = 0; c < NC1; ++c) {
        const uint32_t Ao = (uint32_t)((c & 1) * CHF);
        const uint32_t Bo = (uint32_t)(2 * CHF + (c & 1) * CHF);
        // stage A chunk c from regs (rna)
        {
            float* d = smf + Ao + m2 * CST + h2 * 8;
            *(uint4*)d       = make_uint4(rna(rA0.x), rna(rA0.y), rna(rA0.z), rna(rA0.w));
            *(uint4*)(d + 4) = make_uint4(rna(rA1.x), rna(rA1.y), rna(rA1.z), rna(rA1.w));
        }
        // prefetch chunk c+1
        if (c + 1 < NC1) {
            const int k0n = (c + 1) * 16;
            const int sgn = k0n >> 7;
            const int offn = k0n & 127;
            const float* basen = (sgn == 0) ? seg0 : ((sgn == 1) ? seg1 : seg2);
            const float* pA = basen + (size_t)srow[sgn][m2] * CC + offn + h2 * 8;
            rA0 = __ldg((const float4*)pA);
            rA1 = __ldg((const float4*)pA + 1);
            const float* pB = W1 + (size_t)m2 * K1 + k0n + h2 * 8;
            uint32_t bd = sb + (2 * CHF + ((c + 1) & 1) * CHF + m2 * CST + h2 * 8) * 4;
            CP16(bd, pB); CP16(bd + 16, pB + 4);
            CPCOMMIT();
            CPWAIT1();
        } else {
            CPWAIT0();
        }
        __syncthreads();

#pragma unroll
        for (int ks = 0; ks < 2; ++ks) {
            const int kk = ks * 8;
            uint32_t a[4][4], b[4][2];
#pragma unroll
            for (int na = 0; na < 4; ++na) {
                const int n0 = wn * 32 + na * 8 + r4;
                b[na][0] = __float_as_uint(smf[Bo + n0 * CST + kk + c4]);
                b[na][1] = __float_as_uint(smf[Bo + n0 * CST + kk + c4 + 4]);
            }
#pragma unroll
            for (int ma = 0; ma < 4; ++ma) {
                const int m0 = wm * 64 + ma * 16 + r4;
                a[ma][0] = __float_as_uint(smf[Ao + m0 * CST + kk + c4]);
                a[ma][1] = __float_as_uint(smf[Ao + (m0 + 8) * CST + kk + c4]);
                a[ma][2] = __float_as_uint(smf[Ao + m0 * CST + kk + c4 + 4]);
                a[ma][3] = __float_as_uint(smf[Ao + (m0 + 8) * CST + kk + c4 + 4]);
            }
#pragma unroll
            for (int ma = 0; ma < 4; ++ma)
#pragma unroll
                for (int na = 0; na < 4; ++na) mma_t(acc[ma][na], a[ma], b[na]);
        }
        __syncthreads();
    }

    // ====== hidden: bias + SiLU, rna, store Hs[m][k] (stride 132) =========
    {
#pragma unroll
        for (int ma = 0; ma < 4; ++ma)
#pragma unroll
            for (int rh = 0; rh < 2; ++rh) {
                const int row = wm * 64 + ma * 16 + rh * 8 + r4;
#pragma unroll
                for (int na = 0; na < 4; ++na) {
                    const int col = wn * 32 + na * 8 + c4 * 2;
                    float x0 = acc[ma][na][rh * 2]     + sB1[col];
                    float x1 = acc[ma][na][rh * 2 + 1] + sB1[col + 1];
                    x0 = x0 / (1.f + __expf(-x0));
                    x1 = x1 / (1.f + __expf(-x1));
                    *(uint2*)(smf + OFHf + row * HST + col) = make_uint2(rna(x0), rna(x1));
                    acc[ma][na][rh * 2] = 0.f; acc[ma][na][rh * 2 + 1] = 0.f;
                }
            }
    }

    // ================= GEMM2: hidden @ W2, K16, depth-3 cp.async ==========
    const int NC2 = 8;
    // prologue: issue chunks 0..2 into bufs 0..2
#pragma unroll
    for (int t = 0; t < 3; ++t) {
        const float* pB = W2 + (size_t)m2 * CC + t * 16 + h2 * 8;
        uint32_t bd = sb + ((uint32_t)(t & 3) * CHF + m2 * CST + h2 * 8) * 4;
        CP16(bd, pB); CP16(bd + 16, pB + 4);
        CPCOMMIT();
    }
    for (int c = 0; c < NC2; ++c) {
        const int rem = NC2 - 1 - c;
        if (rem >= 2) { CPWAIT2(); } else if (rem == 1) { CPWAIT1(); } else { CPWAIT0(); }
        __syncthreads();
        if (c + 3 < NC2) {
            const int t = c + 3;
            const float* pB = W2 + (size_t)m2 * CC + t * 16 + h2 * 8;
            uint32_t bd = sb + ((uint32_t)(t & 3) * CHF + m2 * CST + h2 * 8) * 4;
            CP16(bd, pB); CP16(bd + 16, pB + 4);
            CPCOMMIT();
        }
        const uint32_t Bo = (uint32_t)((c & 3) * CHF);
#pragma unroll
        for (int ks = 0; ks < 2; ++ks) {
            const int kk = ks * 8;
            const int kg = c * 16 + kk;
            uint32_t a[4][4], b[4][2];
#pragma unroll
            for (int na = 0; na < 4; ++na) {
                const int n0 = wn * 32 + na * 8 + r4;
                b[na][0] = __float_as_uint(smf[Bo + n0 * CST + kk + c4]);
                b[na][1] = __float_as_uint(smf[Bo + n0 * CST + kk + c4 + 4]);
            }
#pragma unroll
            for (int ma = 0; ma < 4; ++ma) {
                const int m0 = wm * 64 + ma * 16 + r4;
                a[ma][0] = __float_as_uint(smf[OFHf + m0 * HST + kg + c4]);
                a[ma][1] = __float_as_uint(smf[OFHf + (m0 + 8) * HST + kg + c4]);
                a[ma][2] = __float_as_uint(smf[OFHf + m0 * HST + kg + c4 + 4]);
                a[ma][3] = __float_as_uint(smf[OFHf + (m0 + 8) * HST + kg + c4 + 4]);
            }
#pragma unroll
            for (int ma = 0; ma < 4; ++ma)
#pragma unroll
                for (int na = 0; na < 4; ++na) mma_t(acc[ma][na], a[ma], b[na]);
        }
        __syncthreads();
    }

    // ================= epilogue: bias + LayerNorm (+resid / +scatter) =====
    float2* sLN = (float2*)smf;     // aliases dead chunk buffer 0
    {
#pragma unroll
        for (int ma = 0; ma < 4; ++ma)
#pragma unroll
            for (int rh = 0; rh < 2; ++rh) {
                const int rloc = wm * 64 + ma * 16 + rh * 8 + r4;
                float s = 0.f, ss = 0.f;
#pragma unroll
                for (int na = 0; na < 4; ++na) {
                    const int col = wn * 32 + na * 8 + c4 * 2;
                    float y0 = acc[ma][na][rh * 2]     + sB2[col];
                    float y1 = acc[ma][na][rh * 2 + 1] + sB2[col + 1];
                    s += y0 + y1; ss += y0 * y0 + y1 * y1;
                }
                s  += __shfl_xor_sync(0xffffffffu, s, 1);
                ss += __shfl_xor_sync(0xffffffffu, ss, 1);
                s  += __shfl_xor_sync(0xffffffffu, s, 2);
                ss += __shfl_xor_sync(0xffffffffu, ss, 2);
                if (c4 == 0) sLN[rloc * 4 + wn] = make_float2(s, ss);
            }
        __syncthreads();

#pragma unroll
        for (int ma = 0; ma < 4; ++ma)
#pragma unroll
            for (int rh = 0; rh < 2; ++rh) {
                const int rloc = wm * 64 + ma * 16 + rh * 8 + r4;
                const int row  = tile0 + rloc;
                float2 p0 = sLN[rloc * 4 + 0], p1 = sLN[rloc * 4 + 1];
                float2 p2 = sLN[rloc * 4 + 2], p3 = sLN[rloc * 4 + 3];
                const float s  = p0.x + p1.x + p2.x + p3.x;
                const float ss = p0.y + p1.y + p2.y + p3.y;
                const float mu  = s * (1.f / 128.f);
                const float var = ss * (1.f / 128.f) - mu * mu;
                const float rs  = rsqrtf(var + 1e-5f);
                if (row < M) {
                    const int d = EDGE ? saggi[rloc] : 0;
#pragma unroll
                    for (int na = 0; na < 4; ++na) {
                        const int col = wn * 32 + na * 8 + c4 * 2;
                        float y0 = acc[ma][na][rh * 2]     + sB2[col];
                        float y1 = acc[ma][na][rh * 2 + 1] + sB2[col + 1];
                        float v0 = (y0 - mu) * rs * sG[col]     + sBN[col];
                        float v1 = (y1 - mu) * rs * sG[col + 1] + sBN[col + 1];
                        if (!EDGE) {
                            float2 rv = *(const float2*)(resid + (size_t)row * CC + col);
                            v0 += rv.x; v1 += rv.y;
                        }
                        *(float2*)(out + (size_t)row * CC + col) = make_float2(v0, v1);
                        if (EDGE) {
                            float* ap = agg + (size_t)d * CC + col;
                            asm volatile("red.global.add.v2.f32 [%0], {%1,%2};"
                                         :: "l"(ap), "f"(v0), "f"(v1) : "memory");
                        }
                    }
                }
            }
    }
}

// ---- fused setup: zero agg + transpose/round all weight planes ------------
__global__ void setup_kernel(const float* __restrict__ ew1, const float* __restrict__ ew2,
                             const float* __restrict__ nw1, const float* __restrict__ nw2,
                             int n4)
{
    const int gid = blockIdx.x * blockDim.x + threadIdx.x;
    if (gid < n4) ((float4*)g_agg)[gid] = make_float4(0.f, 0.f, 0.f, 0.f);
    if (gid < 7 * CC * CC) {
        int i = gid;
        if (i < 3 * CC * CC) {
            int k = i / CC, n = i % CC;
            g_w1e[n * 3 * CC + k] = __uint_as_float(rna(ew1[i]));
        } else if (i < 4 * CC * CC) {
            int j = i - 3 * CC * CC; int k = j / CC, n = j % CC;
            g_w2e[n * CC + k] = __uint_as_float(rna(ew2[j]));
        } else if (i < 6 * CC * CC) {
            int j = i - 4 * CC * CC; int k = j / CC, n = j % CC;
            g_w1n[n * 2 * CC + k] = __uint_as_float(rna(nw1[j]));
        } else {
            int j = i - 6 * CC * CC; int k = j / CC, n = j % CC;
            g_w2n[n * CC + k] = __uint_as_float(rna(nw2[j]));
        }
    }
}

// -------------------- launch ----------------------------------------------
extern "C" void kernel_launch(void* const* d_in, const int* in_sizes, int n_in,
                              void* d_out, int out_size)
{
    const float* x_src     = (const float*)d_in[0];
    const float* x_dst     = (const float*)d_in[1];
    const float* edge_attr = (const float*)d_in[2];
    const int*   edge_idx  = (const int*)d_in[3];
    const float* eb1 = (const float*)d_in[5];
    const float* eb2 = (const float*)d_in[7];
    const float* eg  = (const float*)d_in[8];
    const float* ebn = (const float*)d_in[9];
    const float* nb1 = (const float*)d_in[11];
    const float* nb2 = (const float*)d_in[13];
    const float* ng  = (const float*)d_in[14];
    const float* nbn = (const float*)d_in[15];

    const int n_src   = in_sizes[0] / CC;
    const int n_dst   = in_sizes[1] / CC;
    const int n_edges = in_sizes[2] / CC;

    const int* src_idx = edge_idx;
    const int* dst_idx = edge_idx + n_edges;

    float* out_src  = (float*)d_out;
    float* out_dst  = out_src + (size_t)n_src * CC;
    float* out_edge = out_dst + (size_t)n_dst * CC;

    float *agg, *w1e, *w2e, *w1n, *w2n;
    cudaGetSymbolAddress((void**)&agg, g_agg);
    cudaGetSymbolAddress((void**)&w1e, g_w1e);
    cudaGetSymbolAddress((void**)&w2e, g_w2e);
    cudaGetSymbolAddress((void**)&w1n, g_w1n);
    cudaGetSymbolAddress((void**)&w2n, g_w2n);

    cudaFuncSetAttribute(mlp_tf32<3, true>,
                         cudaFuncAttributeMaxDynamicSharedMemorySize, SMEM_BYTES);
    cudaFuncSetAttribute(mlp_tf32<2, false>,
                         cudaFuncAttributeMaxDynamicSharedMemorySize, SMEM_BYTES);

    // 1) fused setup: zero agg + weight transpose/round
    {
        int n4 = (n_dst * CC) / 4;
        int nthreads = n4 > 7 * CC * CC ? n4 : 7 * CC * CC;
        setup_kernel<<<(nthreads + 255) / 256, 256>>>(
            (const float*)d_in[4], (const float*)d_in[6],
            (const float*)d_in[10], (const float*)d_in[12], n4);
    }
    // 2) edge MLP + scatter-add into agg
    {
        int nb = (n_edges + MT - 1) / MT;
        mlp_tf32<3, true><<<nb, NTH, SMEM_BYTES>>>(
            x_dst, dst_idx, x_src, src_idx, edge_attr,
            w1e, w2e, eb1, eb2, eg, ebn,
            nullptr, dst_idx, agg, out_edge, n_edges);
    }
    // 3) dst node MLP on [x_dst | agg] + residual
    {
        int nb = (n_dst + MT - 1) / MT;
        mlp_tf32<2, false><<<nb, NTH, SMEM_BYTES>>>(
            x_dst, nullptr, agg, nullptr, nullptr,
            w1n, w2n, nb1, nb2, ng, nbn,
            x_dst, nullptr, nullptr, out_dst, n_dst);
    }
    // 4) src node MLP on [x_src | x_src] + residual
    {
        int nb = (n_src + MT - 1) / MT;
        mlp_tf32<2, false><<<nb, NTH, SMEM_BYTES>>>(
            x_src, nullptr, x_src, nullptr, nullptr,
            w1n, w2n, nb1, nb2, ng, nbn,
            x_src, nullptr, nullptr, out_src, n_src);
    }
}

// round 9
// speedup vs baseline: 1.5280x; 1.5280x over previous
#include <cuda_runtime.h>
#include <cstdint>
#include <cstddef>

#define CC  128
#define MT  128
#define NTH 256

#define CST 20                    // chunk row stride (floats), K16 chunks
#define HST 132                   // hidden [m][k] row stride (floats)
#define CHF (128 * CST)           // 2560 floats per chunk buffer
#define OFHf (4 * CHF)            // hidden offset = 10240 floats
#define SMEM_FLOATS (4 * CHF + 128 * HST)     // 27136
#define SMEM_BYTES  (SMEM_FLOATS * 4)         // 108544

// -------------------- device globals (no allocations allowed) --------------
__device__ float g_agg[40000 * CC];
__device__ float g_w1e[CC * 3 * CC];   // transposed [n][k], tf32-rounded
__device__ float g_w2e[CC * CC];
__device__ float g_w1n[CC * 2 * CC];
__device__ float g_w2n[CC * CC];

// -------------------- helpers ----------------------------------------------
__device__ __forceinline__ uint32_t rna(float x) {
    uint32_t u; asm("cvt.rna.tf32.f32 %0, %1;" : "=r"(u) : "f"(x)); return u;
}
__device__ __forceinline__ uint32_t su32(const void* p) {
    return (uint32_t)__cvta_generic_to_shared(p);
}
__device__ __forceinline__ void mma_t(float* c, const uint32_t* a, const uint32_t* b) {
    asm volatile(
        "mma.sync.aligned.m16n8k8.row.col.f32.tf32.tf32.f32 "
        "{%0,%1,%2,%3}, {%4,%5,%6,%7}, {%8,%9}, {%0,%1,%2,%3};"
        : "+f"(c[0]), "+f"(c[1]), "+f"(c[2]), "+f"(c[3])
        : "r"(a[0]), "r"(a[1]), "r"(a[2]), "r"(a[3]), "r"(b[0]), "r"(b[1]));
}
#define CP16(dst, src) \
    asm volatile("cp.async.cg.shared.global [%0], [%1], 16;" \
                 :: "r"(dst), "l"(src) : "memory")
#define CPCOMMIT() asm volatile("cp.async.commit_group;" ::: "memory")
#define CPWAIT0() asm volatile("cp.async.wait_group 0;" ::: "memory")
#define CPWAIT1() asm volatile("cp.async.wait_group 1;" ::: "memory")
#define CPWAIT2() asm volatile("cp.async.wait_group 2;" ::: "memory")

// -------------------- fused MLP kernel (tf32, pipelined) -------------------
template<int SEGS, bool EDGE>
__global__ __launch_bounds__(NTH, 2)
void mlp_tf32(const float* __restrict__ seg0, const int* __restrict__ idx0,
              const float* __restrict__ seg1, const int* __restrict__ idx1,
              const float* __restrict__ seg2,
              const float* __restrict__ W1, const float* __restrict__ W2,
              const float* __restrict__ B1, const float* __restrict__ B2,
              const float* __restrict__ G,  const float* __restrict__ BN,
              const float* __restrict__ resid,
              const int* __restrict__ aggidx, float* __restrict__ agg,
              float* __restrict__ out, int M)
{
    extern __shared__ __align__(16) float smf[];
    __shared__ int srow[3][MT];
    __shared__ int saggi[MT];
    __shared__ float sB1[CC], sB2[CC], sG[CC], sBN[CC];

    const int tid  = threadIdx.x;
    const int wid  = tid >> 5;
    const int lane = tid & 31;
    const int wm   = wid & 1;
    const int wn   = wid >> 1;
    const int tile0 = blockIdx.x * MT;
    const int K1 = SEGS * CC;
    const int r4 = lane >> 2;
    const int c4 = lane & 3;
    const int m2 = tid >> 1;         // 0..127: A row / weight row
    const int h2 = tid & 1;          // which 8-float half of the 16-k chunk
    const uint32_t sb = su32(smf);

    if (tid < MT) {
        int r = tile0 + tid;
        int rr = (r < M) ? r : (M - 1);
        srow[0][tid] = idx0 ? idx0[rr] : rr;
        srow[1][tid] = idx1 ? idx1[rr] : rr;
        srow[2][tid] = rr;
        if (EDGE) saggi[tid] = aggidx[rr];
        sB1[tid] = B1[tid]; sB2[tid] = B2[tid];
        sG[tid]  = G[tid];  sBN[tid] = BN[tid];
    }

    float acc[4][4][4];
#pragma unroll
    for (int i = 0; i < 4; i++)
#pragma unroll
        for (int j = 0; j < 4; j++)
#pragma unroll
            for (int k = 0; k < 4; k++) acc[i][j][k] = 0.f;

    __syncthreads();

    // ================= GEMM1: [128, SEGS*128] @ W1, K16 pipelined ==========
    const int NC1 = SEGS * 8;
    float4 rA0, rA1;
    // prologue: LDG A chunk 0; cp.async B chunk 0 -> Bbuf0
    {
        const float* pA = seg0 + (size_t)srow[0][m2] * CC + h2 * 8;
        rA0 = __ldg((const float4*)pA);
        rA1 = __ldg((const float4*)pA + 1);
        const float* pB = W1 + (size_t)m2 * K1 + h2 * 8;
        uint32_t bd = sb + (2 * CHF + m2 * CST + h2 * 8) * 4;
        CP16(bd, pB); CP16(bd + 16, pB + 4);
        CPCOMMIT();
    }
    for (int c = 0; c < NC1; ++c) {
        const uint32_t Ao = (uint32_t)((c & 1) * CHF);
        const uint32_t Bo = (uint32_t)(2 * CHF + (c & 1) * CHF);
        // stage A chunk c from regs (rna)
        {
            float* d = smf + Ao + m2 * CST + h2 * 8;
            *(uint4*)d       = make_uint4(rna(rA0.x), rna(rA0.y), rna(rA0.z), rna(rA0.w));
            *(uint4*)(d + 4) = make_uint4(rna(rA1.x), rna(rA1.y), rna(rA1.z), rna(rA1.w));
        }
        // prefetch chunk c+1
        if (c + 1 < NC1) {
            const int k0n = (c + 1) * 16;
            const int sgn = k0n >> 7;
            const int offn = k0n & 127;
            const float* basen = (sgn == 0) ? seg0 : ((sgn == 1) ? seg1 : seg2);
            const float* pA = basen + (size_t)srow[sgn][m2] * CC + offn + h2 * 8;
            rA0 = __ldg((const float4*)pA);
            rA1 = __ldg((const float4*)pA + 1);
            const float* pB = W1 + (size_t)m2 * K1 + k0n + h2 * 8;
            uint32_t bd = sb + (2 * CHF + ((c + 1) & 1) * CHF + m2 * CST + h2 * 8) * 4;
            CP16(bd, pB); CP16(bd + 16, pB + 4);
            CPCOMMIT();
            CPWAIT1();
        } else {
            CPWAIT0();
        }
        __syncthreads();

#pragma unroll
        for (int ks = 0; ks < 2; ++ks) {
            const int kk = ks * 8;
            uint32_t a[4][4], b[4][2];
#pragma unroll
            for (int na = 0; na < 4; ++na) {
                const int n0 = wn * 32 + na * 8 + r4;
                b[na][0] = __float_as_uint(smf[Bo + n0 * CST + kk + c4]);
                b[na][1] = __float_as_uint(smf[Bo + n0 * CST + kk + c4 + 4]);
            }
#pragma unroll
            for (int ma = 0; ma < 4; ++ma) {
                const int m0 = wm * 64 + ma * 16 + r4;
                a[ma][0] = __float_as_uint(smf[Ao + m0 * CST + kk + c4]);
                a[ma][1] = __float_as_uint(smf[Ao + (m0 + 8) * CST + kk + c4]);
                a[ma][2] = __float_as_uint(smf[Ao + m0 * CST + kk + c4 + 4]);
                a[ma][3] = __float_as_uint(smf[Ao + (m0 + 8) * CST + kk + c4 + 4]);
            }
#pragma unroll
            for (int ma = 0; ma < 4; ++ma)
#pragma unroll
                for (int na = 0; na < 4; ++na) mma_t(acc[ma][na], a[ma], b[na]);
        }
        __syncthreads();
    }

    // ====== hidden: bias + SiLU, rna, store Hs[m][k] (stride 132) =========
    {
#pragma unroll
        for (int ma = 0; ma < 4; ++ma)
#pragma unroll
            for (int rh = 0; rh < 2; ++rh) {
                const int row = wm * 64 + ma * 16 + rh * 8 + r4;
#pragma unroll
                for (int na = 0; na < 4; ++na) {
                    const int col = wn * 32 + na * 8 + c4 * 2;
                    float x0 = acc[ma][na][rh * 2]     + sB1[col];
                    float x1 = acc[ma][na][rh * 2 + 1] + sB1[col + 1];
                    x0 = x0 / (1.f + __expf(-x0));
                    x1 = x1 / (1.f + __expf(-x1));
                    *(uint2*)(smf + OFHf + row * HST + col) = make_uint2(rna(x0), rna(x1));
                    acc[ma][na][rh * 2] = 0.f; acc[ma][na][rh * 2 + 1] = 0.f;
                }
            }
    }

    // ================= GEMM2: hidden @ W2, K16, depth-3 cp.async ==========
    const int NC2 = 8;
    // prologue: issue chunks 0..2 into bufs 0..2
#pragma unroll
    for (int t = 0; t < 3; ++t) {
        const float* pB = W2 + (size_t)m2 * CC + t * 16 + h2 * 8;
        uint32_t bd = sb + ((uint32_t)(t & 3) * CHF + m2 * CST + h2 * 8) * 4;
        CP16(bd, pB); CP16(bd + 16, pB + 4);
        CPCOMMIT();
    }
    for (int c = 0; c < NC2; ++c) {
        const int rem = NC2 - 1 - c;
        if (rem >= 2) { CPWAIT2(); } else if (rem == 1) { CPWAIT1(); } else { CPWAIT0(); }
        __syncthreads();
        if (c + 3 < NC2) {
            const int t = c + 3;
            const float* pB = W2 + (size_t)m2 * CC + t * 16 + h2 * 8;
            uint32_t bd = sb + ((uint32_t)(t & 3) * CHF + m2 * CST + h2 * 8) * 4;
            CP16(bd, pB); CP16(bd + 16, pB + 4);
            CPCOMMIT();
        }
        const uint32_t Bo = (uint32_t)((c & 3) * CHF);
#pragma unroll
        for (int ks = 0; ks < 2; ++ks) {
            const int kk = ks * 8;
            const int kg = c * 16 + kk;
            uint32_t a[4][4], b[4][2];
#pragma unroll
            for (int na = 0; na < 4; ++na) {
                const int n0 = wn * 32 + na * 8 + r4;
                b[na][0] = __float_as_uint(smf[Bo + n0 * CST + kk + c4]);
                b[na][1] = __float_as_uint(smf[Bo + n0 * CST + kk + c4 + 4]);
            }
#pragma unroll
            for (int ma = 0; ma < 4; ++ma) {
                const int m0 = wm * 64 + ma * 16 + r4;
                a[ma][0] = __float_as_uint(smf[OFHf + m0 * HST + kg + c4]);
                a[ma][1] = __float_as_uint(smf[OFHf + (m0 + 8) * HST + kg + c4]);
                a[ma][2] = __float_as_uint(smf[OFHf + m0 * HST + kg + c4 + 4]);
                a[ma][3] = __float_as_uint(smf[OFHf + (m0 + 8) * HST + kg + c4 + 4]);
            }
#pragma unroll
            for (int ma = 0; ma < 4; ++ma)
#pragma unroll
                for (int na = 0; na < 4; ++na) mma_t(acc[ma][na], a[ma], b[na]);
        }
        __syncthreads();
    }

    // ================= epilogue: bias + LayerNorm (+resid / +scatter) =====
    float2* sLN = (float2*)smf;     // aliases dead chunk buffer 0
    {
#pragma unroll
        for (int ma = 0; ma < 4; ++ma)
#pragma unroll
            for (int rh = 0; rh < 2; ++rh) {
                const int rloc = wm * 64 + ma * 16 + rh * 8 + r4;
                float s = 0.f, ss = 0.f;
#pragma unroll
                for (int na = 0; na < 4; ++na) {
                    const int col = wn * 32 + na * 8 + c4 * 2;
                    float y0 = acc[ma][na][rh * 2]     + sB2[col];
                    float y1 = acc[ma][na][rh * 2 + 1] + sB2[col + 1];
                    s += y0 + y1; ss += y0 * y0 + y1 * y1;
                }
                s  += __shfl_xor_sync(0xffffffffu, s, 1);
                ss += __shfl_xor_sync(0xffffffffu, ss, 1);
                s  += __shfl_xor_sync(0xffffffffu, s, 2);
                ss += __shfl_xor_sync(0xffffffffu, ss, 2);
                if (c4 == 0) sLN[rloc * 4 + wn] = make_float2(s, ss);
            }
        __syncthreads();

#pragma unroll
        for (int ma = 0; ma < 4; ++ma)
#pragma unroll
            for (int rh = 0; rh < 2; ++rh) {
                const int rloc = wm * 64 + ma * 16 + rh * 8 + r4;
                const int row  = tile0 + rloc;
                float2 p0 = sLN[rloc * 4 + 0], p1 = sLN[rloc * 4 + 1];
                float2 p2 = sLN[rloc * 4 + 2], p3 = sLN[rloc * 4 + 3];
                const float s  = p0.x + p1.x + p2.x + p3.x;
                const float ss = p0.y + p1.y + p2.y + p3.y;
                const float mu  = s * (1.f / 128.f);
                const float var = ss * (1.f / 128.f) - mu * mu;
                const float rs  = rsqrtf(var + 1e-5f);
                if (row < M) {
                    const int d = EDGE ? saggi[rloc] : 0;
#pragma unroll
                    for (int na = 0; na < 4; ++na) {
                        const int col = wn * 32 + na * 8 + c4 * 2;
                        float y0 = acc[ma][na][rh * 2]     + sB2[col];
                        float y1 = acc[ma][na][rh * 2 + 1] + sB2[col + 1];
                        float v0 = (y0 - mu) * rs * sG[col]     + sBN[col];
                        float v1 = (y1 - mu) * rs * sG[col + 1] + sBN[col + 1];
                        if (!EDGE) {
                            float2 rv = *(const float2*)(resid + (size_t)row * CC + col);
                            v0 += rv.x; v1 += rv.y;
                        }
                        *(float2*)(out + (size_t)row * CC + col) = make_float2(v0, v1);
                        if (EDGE) {
                            float* ap = agg + (size_t)d * CC + col;
                            asm volatile("red.global.add.v2.f32 [%0], {%1,%2};"
                                         :: "l"(ap), "f"(v0), "f"(v1) : "memory");
                        }
                    }
                }
            }
    }
}

// ---- fused setup: zero agg + transpose/round all weight planes ------------
__global__ void setup_kernel(const float* __restrict__ ew1, const float* __restrict__ ew2,
                             const float* __restrict__ nw1, const float* __restrict__ nw2,
                             int n4)
{
    const int gid = blockIdx.x * blockDim.x + threadIdx.x;
    if (gid < n4) ((float4*)g_agg)[gid] = make_float4(0.f, 0.f, 0.f, 0.f);
    if (gid < 7 * CC * CC) {
        int i = gid;
        if (i < 3 * CC * CC) {
            int k = i / CC, n = i % CC;
            g_w1e[n * 3 * CC + k] = __uint_as_float(rna(ew1[i]));
        } else if (i < 4 * CC * CC) {
            int j = i - 3 * CC * CC; int k = j / CC, n = j % CC;
            g_w2e[n * CC + k] = __uint_as_float(rna(ew2[j]));
        } else if (i < 6 * CC * CC) {
            int j = i - 4 * CC * CC; int k = j / CC, n = j % CC;
            g_w1n[n * 2 * CC + k] = __uint_as_float(rna(nw1[j]));
        } else {
            int j = i - 6 * CC * CC; int k = j / CC, n = j % CC;
            g_w2n[n * CC + k] = __uint_as_float(rna(nw2[j]));
        }
    }
}

// -------------------- launch ----------------------------------------------
extern "C" void kernel_launch(void* const* d_in, const int* in_sizes, int n_in,
                              void* d_out, int out_size)
{
    const float* x_src     = (const float*)d_in[0];
    const float* x_dst     = (const float*)d_in[1];
    const float* edge_attr = (const float*)d_in[2];
    const int*   edge_idx  = (const int*)d_in[3];
    const float* eb1 = (const float*)d_in[5];
    const float* eb2 = (const float*)d_in[7];
    const float* eg  = (const float*)d_in[8];
    const float* ebn = (const float*)d_in[9];
    const float* nb1 = (const float*)d_in[11];
    const float* nb2 = (const float*)d_in[13];
    const float* ng  = (const float*)d_in[14];
    const float* nbn = (const float*)d_in[15];

    const int n_src   = in_sizes[0] / CC;
    const int n_dst   = in_sizes[1] / CC;
    const int n_edges = in_sizes[2] / CC;

    const int* src_idx = edge_idx;
    const int* dst_idx = edge_idx + n_edges;

    float* out_src  = (float*)d_out;
    float* out_dst  = out_src + (size_t)n_src * CC;
    float* out_edge = out_dst + (size_t)n_dst * CC;

    float *agg, *w1e, *w2e, *w1n, *w2n;
    cudaGetSymbolAddress((void**)&agg, g_agg);
    cudaGetSymbolAddress((void**)&w1e, g_w1e);
    cudaGetSymbolAddress((void**)&w2e, g_w2e);
    cudaGetSymbolAddress((void**)&w1n, g_w1n);
    cudaGetSymbolAddress((void**)&w2n, g_w2n);

    cudaFuncSetAttribute(mlp_tf32<3, true>,
                         cudaFuncAttributeMaxDynamicSharedMemorySize, SMEM_BYTES);
    cudaFuncSetAttribute(mlp_tf32<2, false>,
                         cudaFuncAttributeMaxDynamicSharedMemorySize, SMEM_BYTES);

    // 1) fused setup: zero agg + weight transpose/round
    {
        int n4 = (n_dst * CC) / 4;
        int nthreads = n4 > 7 * CC * CC ? n4 : 7 * CC * CC;
        setup_kernel<<<(nthreads + 255) / 256, 256>>>(
            (const float*)d_in[4], (const float*)d_in[6],
            (const float*)d_in[10], (const float*)d_in[12], n4);
    }
    // 2) edge MLP + scatter-add into agg
    {
        int nb = (n_edges + MT - 1) / MT;
        mlp_tf32<3, true><<<nb, NTH, SMEM_BYTES>>>(
            x_dst, dst_idx, x_src, src_idx, edge_attr,
            w1e, w2e, eb1, eb2, eg, ebn,
            nullptr, dst_idx, agg, out_edge, n_edges);
    }
    // 3) dst node MLP on [x_dst | agg] + residual
    {
        int nb = (n_dst + MT - 1) / MT;
        mlp_tf32<2, false><<<nb, NTH, SMEM_BYTES>>>(
            x_dst, nullptr, agg, nullptr, nullptr,
            w1n, w2n, nb1, nb2, ng, nbn,
            x_dst, nullptr, nullptr, out_dst, n_dst);
    }
    // 4) src node MLP on [x_src | x_src] + residual
    {
        int nb = (n_src + MT - 1) / MT;
        mlp_tf32<2, false><<<nb, NTH, SMEM_BYTES>>>(
            x_src, nullptr, x_src, nullptr, nullptr,
            w1n, w2n, nb1, nb2, ng, nbn,
            x_src, nullptr, nullptr, out_src, n_src);
    }
}